// round 1
// baseline (speedup 1.0000x reference)
#include <cuda_runtime.h>
#include <cstdint>

// ---------------------------------------------------------------------------
// SpikeFP32Embedding: out[tok] = weight_pulse[token_ids[tok]]
//   token_ids  : [16384]  (int64 per reference, int32 if JAX x64 was off)
//   weight_pulse: [32768, 128, 32] fp32  -> 16 KB per row
//   out        : [16384, 128, 32] fp32
// Pure row gather; memory-bound. 256 MB read + 256 MB write.
// ---------------------------------------------------------------------------

#define ROW_F4   1024   // 128*32 floats = 1024 float4 per row
#define THREADS  256
#define F4_PER_T (ROW_F4 / THREADS)   // 4

__device__ int g_ids_are_i64;  // 1 if token buffer is int64, 0 if int32

// One block scans the id buffer reinterpreted as u64 words.
// If layout is int64: every word is a token id in [0, 32768) -> stays valid.
// If layout is int32: word = tok[2k] | tok[2k+1]<<32; any nonzero odd token
// pushes it >= 2^32. Over 8192 words the false-negative probability is ~0.
__global__ void detect_dtype_kernel(const unsigned long long* __restrict__ ids,
                                    int n_words) {
    __shared__ int bad;
    if (threadIdx.x == 0) bad = 0;
    __syncthreads();
    int local_bad = 0;
    for (int i = threadIdx.x; i < n_words; i += blockDim.x) {
        if (ids[i] >= 32768ULL) local_bad = 1;
    }
    if (local_bad) bad = 1;
    __syncthreads();
    if (threadIdx.x == 0) g_ids_are_i64 = bad ? 0 : 1;
}

__global__ __launch_bounds__(THREADS)
void gather_rows_kernel(const void* __restrict__ ids,
                        const float4* __restrict__ w,
                        float4* __restrict__ out) {
    const int tok = blockIdx.x;

    long long id;
    if (g_ids_are_i64) {
        id = __ldg((const long long*)ids + tok);
    } else {
        id = (long long)__ldg((const int*)ids + tok);
    }

    const float4* __restrict__ src = w   + (size_t)id  * ROW_F4;
    float4*       __restrict__ dst = out + (size_t)tok * ROW_F4;

    const int t = threadIdx.x;
#pragma unroll
    for (int i = 0; i < F4_PER_T; i++) {
        const int idx = t + i * THREADS;
        float4 v = __ldg(&src[idx]);
        __stwt(&dst[idx], v);   // streaming store: output has zero reuse,
                                // keep L2 for the gathered weight rows
    }
}

extern "C" void kernel_launch(void* const* d_in, const int* in_sizes, int n_in,
                              void* d_out, int out_size) {
    const void*   ids = d_in[0];
    const float4* w   = (const float4*)d_in[1];
    float4*       out = (float4*)d_out;

    const int n_tokens = in_sizes[0];          // 16384

    // Detection reads n_tokens/2 u64 words: exactly the int32 buffer size,
    // and the first half of the int64 buffer — in-bounds either way.
    detect_dtype_kernel<<<1, 256>>>((const unsigned long long*)ids,
                                    n_tokens / 2);

    gather_rows_kernel<<<n_tokens, THREADS>>>(ids, w, out);
}

// round 2
// speedup vs baseline: 1.1696x; 1.1696x over previous
#include <cuda_runtime.h>
#include <cstdint>

// ---------------------------------------------------------------------------
// SpikeFP32Embedding: out[tok] = weight_pulse[token_ids[tok]]
//   token_ids   : [16384]  (int64 per reference; int32 if JAX x64 was off)
//   weight_pulse: [32768, 128, 32] fp32  -> 16 KB per row
//   out         : [16384, 128, 32] fp32
// Pure row gather; memory-bound: ~205 MB unique reads + 256 MB writes.
//
// Single fused kernel: per-block inline dtype detection (8 L2-broadcast u64
// loads + 1 barrier) replaces the previous serialized 1-block detect kernel,
// which cost ~22 us of the 98.4 us total.
// ---------------------------------------------------------------------------

#define ROW_F4   1024   // 128*32 floats = 1024 float4 per row
#define THREADS  256
#define F4_PER_T (ROW_F4 / THREADS)   // 4

__global__ __launch_bounds__(THREADS)
void gather_rows_kernel(const void* __restrict__ ids,
                        const float4* __restrict__ w,
                        float4* __restrict__ out) {
    // ---- inline dtype detection -------------------------------------------
    // Reinterpret the id buffer as u64 words. All legal tokens < 2^15, so:
    //   int64 layout: words 1..8 are tokens 1..8  -> OR of them < 2^15.
    //   int32 layout: word i = tok[2i] | tok[2i+1]<<32; a nonzero token at
    //   any odd index 3..17 pushes the OR >= 2^32.
    // False-negative probability: (1/32000)^8 ~ 0. These 8 loads hit L2
    // (broadcast across all 16384 blocks) after the first block touches them.
    __shared__ int s_i64;
    if (threadIdx.x == 0) {
        const unsigned long long* w64 = (const unsigned long long*)ids;
        unsigned long long m = 0;
#pragma unroll
        for (int i = 1; i <= 8; i++) m |= __ldg(w64 + i);
        s_i64 = (m < 32768ULL) ? 1 : 0;
    }
    __syncthreads();

    // ---- row gather ---------------------------------------------------------
    const int tok = blockIdx.x;

    long long id;
    if (s_i64) {
        id = __ldg((const long long*)ids + tok);
    } else {
        id = (long long)__ldg((const int*)ids + tok);
    }

    const float4* __restrict__ src = w   + (size_t)id  * ROW_F4;
    float4*       __restrict__ dst = out + (size_t)tok * ROW_F4;

    const int t = threadIdx.x;
#pragma unroll
    for (int i = 0; i < F4_PER_T; i++) {
        const int idx = t + i * THREADS;
        float4 v = __ldg(&src[idx]);
        __stwt(&dst[idx], v);   // streaming store: output has zero reuse,
                                // keep L2 capacity for gathered weight rows
    }
}

extern "C" void kernel_launch(void* const* d_in, const int* in_sizes, int n_in,
                              void* d_out, int out_size) {
    const void*   ids = d_in[0];
    const float4* w   = (const float4*)d_in[1];
    float4*       out = (float4*)d_out;

    const int n_tokens = in_sizes[0];   // 16384

    gather_rows_kernel<<<n_tokens, THREADS>>>(ids, w, out);
}